// round 16
// baseline (speedup 1.0000x reference)
#include <cuda_runtime.h>
#include <cuda_bf16.h>
#include <math_constants.h>

// Problem constants
#define T_TOKENS 4096
#define HIDDEN   2048
#define N_EXP    8
#define H4       (HIDDEN / 4)          // 512 float4 per hidden row

// Output layout (floats), outputs concatenated:
//   [0, 32768)                router_scores [E, T]
//   [32768, +67108864)        router_indices [E*T, H] (value = t, as float)
//   [67141632, 67174400)      router_probs [E*T, 1] == scores flattened
#define SCORES_OFF 0
#define IDX_OFF    (N_EXP * T_TOKENS)                       // 32768
#define IDX_ELEMS  ((size_t)N_EXP * T_TOKENS * HIDDEN)      // 67108864
#define IDX_F4     (IDX_ELEMS / 4)                          // 16,777,216
#define IDX_F8     (IDX_ELEMS / 8)                          // 8,388,608
#define PROBS_OFF  (IDX_OFF + IDX_ELEMS)                    // 67141632

// Balanced-wave grid (888*19 = 16872) with STATIC indexing (R15 config),
// fill stores widened to 256-bit (st.global.cs.v8.f32, sm_100+):
//   ids [0, 512)       logits blocks (R8 config, unchanged)
//   ids [512, 16872)   fill blocks: 512 v8 (= 1024 f4) region each,
//                      4 v8-stores/thread, zero bound checks.
//   remainder: 16,777,216 f4 - 16360*1024 = 24576 f4 = 12288 v8
//              -> first 96 fill blocks do 1 extra v8 store each.
#define LOGITS_BLOCKS 512
#define TPW 2
#define FILL_BLOCKS 16360
#define GRID_BLOCKS (LOGITS_BLOCKS + FILL_BLOCKS)           // 16872 = 888*19
#define FILL_F8_PER_BLOCK 512
#define MAIN_F8 ((size_t)FILL_BLOCKS * FILL_F8_PER_BLOCK)   // 8,376,320
#define EXTRA_F8 (IDX_F8 - MAIN_F8)                         // 12,288
#define EXTRA_BLOCKS (EXTRA_F8 / 128)                       // 96

// 256-bit streaming store of a replicated value. Each v8 covers float4
// indices {2k, 2k+1}; rows are 512 f4 (even), so never straddles a row.
__device__ __forceinline__ void st_v8_bcast(float* p, float v) {
    asm volatile(
        "st.global.cs.v8.f32 [%0], {%1, %1, %1, %1, %1, %1, %1, %1};"
        :: "l"(p), "f"(v) : "memory");
}

__global__ __launch_bounds__(128, 6)
void router_fused_kernel(const float* __restrict__ hs,
                         const float* __restrict__ wr,
                         float* __restrict__ out) {
    const unsigned bid = blockIdx.x;

    if (bid >= LOGITS_BLOCKS) {
        // ---------------- fill branch: 256-bit static stores ----------------
        const unsigned fid = bid - LOGITS_BLOCKS;      // 0 .. 16359
        float* __restrict__ outf = out + IDX_OFF;
        const size_t base = (size_t)fid * FILL_F8_PER_BLOCK + threadIdx.x;
#pragma unroll
        for (int j = 0; j < 4; j++) {
            const size_t k = base + (size_t)j * 128;        // v8 index
            // row t = (f4_index >> 9) = (2k >> 9) = k >> 8
            const float v = (float)((k >> 8) & (T_TOKENS - 1));
            st_v8_bcast(outf + k * 8, v);
        }
        // remainder: first 96 fill blocks store one extra v8 each
        if (fid < EXTRA_BLOCKS) {
            const size_t k = MAIN_F8 + (size_t)fid * 128 + threadIdx.x;
            const float v = (float)((k >> 8) & (T_TOKENS - 1));
            st_v8_bcast(outf + k * 8, v);
        }
        return;
    }

    // ------------------------- logits branch -------------------------
    const int warp = threadIdx.x >> 5;
    const int lane = threadIdx.x & 31;
    const int t0 = ((int)bid * 4 + warp) * TPW;      // 2 tokens per warp

    const float4* __restrict__ hs4 = (const float4*)hs;
    const float4* __restrict__ w4  = (const float4*)wr;

    float acc[TPW][N_EXP];
#pragma unroll
    for (int a = 0; a < TPW; a++)
#pragma unroll
        for (int e = 0; e < N_EXP; e++) acc[a][e] = 0.f;

#pragma unroll 2
    for (int ii = 0; ii < H4 / 32; ii++) {           // 16 iterations
        const int i = ii * 32 + lane;
        float4 x[TPW];
#pragma unroll
        for (int a = 0; a < TPW; a++)
            x[a] = hs4[(size_t)(t0 + a) * H4 + i];
#pragma unroll
        for (int e = 0; e < N_EXP; e++) {
            const float4 wv = __ldg(&w4[e * H4 + i]);
#pragma unroll
            for (int a = 0; a < TPW; a++) {
                acc[a][e] += x[a].x * wv.x + x[a].y * wv.y
                           + x[a].z * wv.z + x[a].w * wv.w;
            }
        }
    }

    // butterfly warp reduction
#pragma unroll
    for (int a = 0; a < TPW; a++)
#pragma unroll
        for (int e = 0; e < N_EXP; e++)
#pragma unroll
            for (int o = 16; o > 0; o >>= 1)
                acc[a][e] += __shfl_xor_sync(0xffffffffu, acc[a][e], o);

    if (lane == 0) {
#pragma unroll
        for (int a = 0; a < TPW; a++) {
            const int t = t0 + a;
            float b1 = -CUDART_INF_F; int i1 = 0;
#pragma unroll
            for (int e = 0; e < N_EXP; e++)
                if (acc[a][e] > b1) { b1 = acc[a][e]; i1 = e; }
            float b2 = -CUDART_INF_F; int i2 = -1;
#pragma unroll
            for (int e = 0; e < N_EXP; e++)
                if (e != i1 && acc[a][e] > b2) { b2 = acc[a][e]; i2 = e; }

            const float s1 = 1.f / (1.f + __expf(-b1));
            const float s2 = 1.f / (1.f + __expf(-b2));
#pragma unroll
            for (int e = 0; e < N_EXP; e++) {
                const float s = (e == i1) ? s1 : ((e == i2) ? s2 : 0.f);
                out[SCORES_OFF + (size_t)e * T_TOKENS + t] = s;
                out[PROBS_OFF  + (size_t)e * T_TOKENS + t] = s;
            }
        }
    }
}

extern "C" void kernel_launch(void* const* d_in, const int* in_sizes, int n_in,
                              void* d_out, int out_size) {
    const float* hs = (const float*)d_in[0];  // [T, H] fp32
    const float* wr = (const float*)d_in[1];  // [E, H] fp32
    float* out = (float*)d_out;

    router_fused_kernel<<<GRID_BLOCKS, 128>>>(hs, wr, out);
}

// round 17
// speedup vs baseline: 1.1787x; 1.1787x over previous
#include <cuda_runtime.h>
#include <cuda_bf16.h>
#include <math_constants.h>

// Problem constants
#define T_TOKENS 4096
#define HIDDEN   2048
#define N_EXP    8
#define H4       (HIDDEN / 4)          // 512 float4 per hidden row

// Output layout (floats), outputs concatenated:
//   [0, 32768)                router_scores [E, T]
//   [32768, +67108864)        router_indices [E*T, H] (value = t, as float)
//   [67141632, 67174400)      router_probs [E*T, 1] == scores flattened
#define SCORES_OFF 0
#define IDX_OFF    (N_EXP * T_TOKENS)                       // 32768
#define IDX_ELEMS  ((size_t)N_EXP * T_TOKENS * HIDDEN)      // 67108864
#define IDX_F4     (IDX_ELEMS / 4)                          // 16,777,216
#define PROBS_OFF  (IDX_OFF + IDX_ELEMS)                    // 67141632

// FINAL (locked, R15 config — measured 43.46us wall, 42.37us ncu, 72.3% DRAM):
// Balanced-wave grid: concurrency = 6 CTA/SM * 148 SM = 888; 888*19 = 16872.
//   ids [0, 512)       logits blocks: 4 warps x 2 tokens/warp (TPW=2 is the
//                      measured optimum: 5 LDG.128/token, short CTAs, 80 regs)
//   ids [512, 16872)   fill blocks: static 1024-f4 region, 8 STG.128/thread;
//                      first 192 fill blocks cover the 24576-f4 remainder
//                      with one extra predicated store each.
// Logits confined to wave 1 (hs reads overlap early fill writes); short fill
// CTAs backfill; STG.128 + __stcs is the robust store path (v8 and
// grid-stride variants regressed wall clock).
#define LOGITS_BLOCKS 512
#define TPW 2
#define FILL_BLOCKS 16360
#define GRID_BLOCKS (LOGITS_BLOCKS + FILL_BLOCKS)           // 16872 = 888*19
#define FILL_F4_PER_BLOCK 1024
#define MAIN_F4 ((size_t)FILL_BLOCKS * FILL_F4_PER_BLOCK)   // 16,752,640
#define EXTRA_F4 (IDX_F4 - MAIN_F4)                         // 24,576
#define EXTRA_BLOCKS (EXTRA_F4 / 128)                       // 192

__global__ __launch_bounds__(128, 6)
void router_fused_kernel(const float* __restrict__ hs,
                         const float* __restrict__ wr,
                         float* __restrict__ out) {
    const unsigned bid = blockIdx.x;

    if (bid >= LOGITS_BLOCKS) {
        // ------------------ fill branch: static indexing ------------------
        const unsigned fid = bid - LOGITS_BLOCKS;      // 0 .. 16359
        float4* __restrict__ out4 = (float4*)(out + IDX_OFF);
        const size_t base = (size_t)fid * FILL_F4_PER_BLOCK + threadIdx.x;
#pragma unroll
        for (int j = 0; j < 8; j++) {
            const size_t i = base + (size_t)j * 128;
            const float v = (float)((i >> 9) & (T_TOKENS - 1));
            __stcs(&out4[i], make_float4(v, v, v, v));
        }
        // remainder: first 192 fill blocks store one extra float4 each
        if (fid < EXTRA_BLOCKS) {
            const size_t i = MAIN_F4 + (size_t)fid * 128 + threadIdx.x;
            const float v = (float)((i >> 9) & (T_TOKENS - 1));
            __stcs(&out4[i], make_float4(v, v, v, v));
        }
        return;
    }

    // ------------------------- logits branch -------------------------
    const int warp = threadIdx.x >> 5;
    const int lane = threadIdx.x & 31;
    const int t0 = ((int)bid * 4 + warp) * TPW;      // 2 tokens per warp

    const float4* __restrict__ hs4 = (const float4*)hs;
    const float4* __restrict__ w4  = (const float4*)wr;

    float acc[TPW][N_EXP];
#pragma unroll
    for (int a = 0; a < TPW; a++)
#pragma unroll
        for (int e = 0; e < N_EXP; e++) acc[a][e] = 0.f;

#pragma unroll 2
    for (int ii = 0; ii < H4 / 32; ii++) {           // 16 iterations
        const int i = ii * 32 + lane;
        float4 x[TPW];
#pragma unroll
        for (int a = 0; a < TPW; a++)
            x[a] = hs4[(size_t)(t0 + a) * H4 + i];
#pragma unroll
        for (int e = 0; e < N_EXP; e++) {
            const float4 wv = __ldg(&w4[e * H4 + i]);
#pragma unroll
            for (int a = 0; a < TPW; a++) {
                acc[a][e] += x[a].x * wv.x + x[a].y * wv.y
                           + x[a].z * wv.z + x[a].w * wv.w;
            }
        }
    }

    // butterfly warp reduction
#pragma unroll
    for (int a = 0; a < TPW; a++)
#pragma unroll
        for (int e = 0; e < N_EXP; e++)
#pragma unroll
            for (int o = 16; o > 0; o >>= 1)
                acc[a][e] += __shfl_xor_sync(0xffffffffu, acc[a][e], o);

    if (lane == 0) {
#pragma unroll
        for (int a = 0; a < TPW; a++) {
            const int t = t0 + a;
            float b1 = -CUDART_INF_F; int i1 = 0;
#pragma unroll
            for (int e = 0; e < N_EXP; e++)
                if (acc[a][e] > b1) { b1 = acc[a][e]; i1 = e; }
            float b2 = -CUDART_INF_F; int i2 = -1;
#pragma unroll
            for (int e = 0; e < N_EXP; e++)
                if (e != i1 && acc[a][e] > b2) { b2 = acc[a][e]; i2 = e; }

            const float s1 = 1.f / (1.f + __expf(-b1));
            const float s2 = 1.f / (1.f + __expf(-b2));
#pragma unroll
            for (int e = 0; e < N_EXP; e++) {
                const float s = (e == i1) ? s1 : ((e == i2) ? s2 : 0.f);
                out[SCORES_OFF + (size_t)e * T_TOKENS + t] = s;
                out[PROBS_OFF  + (size_t)e * T_TOKENS + t] = s;
            }
        }
    }
}

extern "C" void kernel_launch(void* const* d_in, const int* in_sizes, int n_in,
                              void* d_out, int out_size) {
    const float* hs = (const float*)d_in[0];  // [T, H] fp32
    const float* wr = (const float*)d_in[1];  // [E, H] fp32
    float* out = (float*)d_out;

    router_fused_kernel<<<GRID_BLOCKS, 128>>>(hs, wr, out);
}